// round 13
// baseline (speedup 1.0000x reference)
#include <cuda_runtime.h>
#include <cuda_bf16.h>

#define TPB     256
#define SPLIT   8
#define MAX_B   1024
#define MAX_NT  2048

// cross-kernel scratch (allocation-free). g_key/g_cnt zero at load and
// self-reset by the finisher -> deterministic across graph replays.
__device__ unsigned long long g_key[MAX_B];
__device__ int                g_cnt[MAX_B];
__device__ int                g_list[MAX_B];
__device__ int                g_nrej;

// ---------- Kernel A: token-parallel gather + per-request scan --------------
__global__ void __launch_bounds__(512)
scan_compact(const float* __restrict__ draft_probs,
             const float* __restrict__ target_probs,
             const float* __restrict__ uniform_probs,
             const int*   __restrict__ draft_token_ids,
             const int*   __restrict__ cu,
             const int*   __restrict__ bonus,
             float*       __restrict__ out,
             int B, int NT, int V, int L)
{
    __shared__ int   sid[MAX_NT];
    __shared__ float stp[MAX_NT];
    __shared__ float sdp[MAX_NT];
    __shared__ float su [MAX_NT];
    __shared__ int   scu[MAX_B];
    __shared__ int   wcnt[16];

    const int tid = threadIdx.x;

    // round 1: cu and token ids (independent, concurrent)
    for (int r = tid; r < B; r += 512) scu[r] = __ldg(&cu[r]);
    for (int t = tid; t < NT; t += 512) sid[t] = __ldg(&draft_token_ids[t]);
    __syncthreads();

    // round 2: prob/uniform gathers, token-parallel (one latency round)
    for (int t = tid; t < NT; t += 512) {
        const int idv = sid[t];
        stp[t] = __ldg(&target_probs[(size_t)t * V + idv]);
        sdp[t] = __ldg(&draft_probs [(size_t)t * V + idv]);
        su [t] = __ldg(&uniform_probs[t]);
    }
    __syncthreads();

    // per-request scan (threads 0..B-1), faithful to reference
    const int r      = tid;
    const bool activ = (r < B);
    int start = 0, end = 0;
    if (activ) { start = (r == 0) ? 0 : scu[r - 1]; end = scu[r]; }
    const int nd  = end - start;
    const int lim = (nd < L) ? nd : L;

    float pi = 1.0f, U = 1.0f;
    int last = -1;
    for (int j = 0; j < lim; j++) {
        const int t = start + j;
        const float dpj = sdp[t];
        const float ratio = (dpj > 0.0f) ? (stp[t] / dpj) : 1.0f;
        pi = fminf(pi * ratio, 1.0f);
        U *= su[t];
        if ((dpj > 0.0f) && (pi >= U)) last = j;
    }

    const int rejected  = (activ && nd > 0 && last != nd - 1) ? 1 : 0;
    const int write_col = rejected ? (last + 1) : nd;

    if (activ) {
        float* orow = out + (size_t)r * (L + 1);
        for (int j = 0; j <= L; j++) {
            float v = -1.0f;
            if (j < L && j <= last) v = (float)sid[start + j];
            orow[j] = v;
        }
        if (!rejected) orow[write_col] = (float)__ldg(&bonus[r]);
    }

    int rec = start + last + 1;
    rec = (rec < 0) ? 0 : rec;
    rec = (rec > NT - 1) ? (NT - 1) : rec;

    // compaction (ballot + cross-warp prefix; deterministic order)
    const int warp = tid >> 5, lane = tid & 31;
    const unsigned ball = __ballot_sync(0xffffffffu, rejected);
    const int rank = __popc(ball & ((1u << lane) - 1));
    if (lane == 0) wcnt[warp] = __popc(ball);
    __syncthreads();
    int base = 0, total = 0;
    #pragma unroll
    for (int w = 0; w < 16; w++) {
        if (w < warp) base += wcnt[w];
        total += wcnt[w];
    }
    if (rejected)
        g_list[base + rank] = r | (write_col << 8) | (rec << 12);
    if (tid == 0) g_nrej = total;
}

// ---------- Kernel B: single-volley max-tree argmax -------------------------
// Per block: C float4 (C = chunk/4). Per thread: KF unmasked + optional 1
// masked load, all front-issued (first consumer is a pure fmax tree, so ptxas
// cannot sink the loads). Index recovered afterwards via m[k]==M scan + one
// L1-hit reload of the winning float4.
__global__ void __launch_bounds__(TPB)
argmax_kernel(const float* __restrict__ target_probs,
              float* __restrict__ out, int V, int L)
{
    const int row = blockIdx.x / SPLIT;
    if (row >= g_nrej) return;
    const int s   = blockIdx.x % SPLIT;
    const int tid = threadIdx.x;

    const int e   = g_list[row];               // broadcast L2 read
    const int r   = e & 0xff;
    const int pos = (e >> 8) & 0xf;
    const int rec = e >> 12;

    const int chunk = (((V + SPLIT - 1) / SPLIT) + 3) & ~3;   // 4-aligned floats
    const int nact  = (V + chunk - 1) / chunk;
    if (s >= nact) return;
    const int beg = s * chunk;
    const int fin = min(V, beg + chunk);

    const float*  rowp = target_probs + (size_t)rec * V;
    const float4* row4 = reinterpret_cast<const float4*>(rowp);
    const int n4beg = beg >> 2;
    const int n4end = fin >> 2;
    const int n4    = n4end - n4beg;           // float4 count in this chunk

    float best = -1.0f;                        // probs >= 0
    int   bb4  = -1;                           // winning float4 index (global)

    // number of full unmasked passes every thread can do
    const int KF = n4 / TPB;                   // e.g. 4000/256 = 15
    {
        float m[20];                           // per-f4 maxima (KF<=19 assumed)
        const float4* p = row4 + n4beg + tid;

        // front-issued unmasked loads; v dies into max4 immediately
        #pragma unroll
        for (int k = 0; k < 20; k++) {
            if (k >= KF) break;
            const float4 v = __ldg(p + k * TPB);
            m[k] = fmaxf(fmaxf(v.x, v.y), fmaxf(v.z, v.w));
        }
        // masked extra element
        float mx = -1.0f;
        const int xi = n4beg + tid + KF * TPB;
        const bool has_x = (xi < n4end);
        if (has_x) {
            const float4 v = __ldg(&row4[xi]);
            mx = fmaxf(fmaxf(v.x, v.y), fmaxf(v.z, v.w));
        }

        // tree max over the group
        float M = mx;
        #pragma unroll
        for (int k = 0; k < 20; k++) {
            if (k >= KF) break;
            M = fmaxf(M, m[k]);
        }

        if (M > best) {
            best = M;
            // smallest k with m[k]==M  (global index grows with k)
            int kwin = has_x && (mx == M) ? KF : -1;
            #pragma unroll
            for (int k = 19; k >= 0; k--) {
                if (k < KF && m[k] == M) kwin = k;
            }
            bb4 = n4beg + tid + kwin * TPB;
        }
    }

    // decode winning lane (one L1-hit reload), first-occurrence within float4
    int bidx = 0x7fffffff;
    if (bb4 >= 0) {
        const float4 v = __ldg(&row4[bb4]);
        bidx = (bb4 << 2) + ((v.x == best) ? 0 : (v.y == best) ? 1
                           : (v.z == best) ? 2 : 3);
    }

    // warp reduce (min-index tie-break -> global first occurrence)
    #pragma unroll
    for (int off = 16; off > 0; off >>= 1) {
        const float ov = __shfl_down_sync(0xffffffffu, best, off);
        const int   oi = __shfl_down_sync(0xffffffffu, bidx, off);
        if (ov > best || (ov == best && oi < bidx)) { best = ov; bidx = oi; }
    }

    __shared__ float wv[TPB / 32];
    __shared__ int   wi[TPB / 32];
    const int warp = tid >> 5, lane = tid & 31;
    if (lane == 0) { wv[warp] = best; wi[warp] = bidx; }
    __syncthreads();

    if (tid == 0) {
        #pragma unroll
        for (int w = 1; w < TPB / 32; w++) {
            if (wv[w] > best || (wv[w] == best && wi[w] < bidx)) {
                best = wv[w]; bidx = wi[w];
            }
        }
        // pack: prob bits (monotone for >=0 floats) | ~index (ties -> min idx)
        const unsigned long long key =
            ((unsigned long long)__float_as_uint(best) << 32) |
            (unsigned long long)(~(unsigned)bidx);
        atomicMax(&g_key[r], key);
        __threadfence();
        const int old = atomicAdd(&g_cnt[r], 1);
        if (old == nact - 1) {                       // last finisher
            const unsigned long long k = atomicMax(&g_key[r], 0ULL);
            const int idx = (int)(~(unsigned)(k & 0xffffffffULL));
            out[(size_t)r * (L + 1) + pos] = (float)idx;
            g_key[r] = 0ULL;                         // self-reset for replay
            g_cnt[r] = 0;
        }
    }
}

extern "C" void kernel_launch(void* const* d_in, const int* in_sizes, int n_in,
                              void* d_out, int out_size) {
    const float* draft_probs     = (const float*)d_in[0];
    const float* target_probs    = (const float*)d_in[1];
    const float* uniform_probs   = (const float*)d_in[2];
    const int*   draft_token_ids = (const int*)  d_in[3];
    const int*   cu              = (const int*)  d_in[4];
    const int*   bonus           = (const int*)  d_in[5];
    float*       out             = (float*)d_out;

    const int NT = in_sizes[3];
    const int B  = in_sizes[4];
    const int V  = in_sizes[0] / NT;
    const int L  = out_size / B - 1;

    scan_compact<<<1, 512>>>(draft_probs, target_probs, uniform_probs,
                             draft_token_ids, cu, bonus, out, B, NT, V, L);
    argmax_kernel<<<B * SPLIT, TPB>>>(target_probs, out, V, L);
}

// round 14
// speedup vs baseline: 1.1597x; 1.1597x over previous
#include <cuda_runtime.h>
#include <cuda_bf16.h>

#define TPB     256
#define GSPLIT  8      // generic-path split
#define SSPLIT  25     // specialized-path split (V=128000)
#define MAX_B   1024
#define MAX_NT  2048
#define BATCH   8

// cross-kernel scratch (allocation-free). g_key/g_cnt zero at load and
// self-reset by the finisher -> deterministic across graph replays.
__device__ unsigned long long g_key[MAX_B];
__device__ int                g_cnt[MAX_B];
__device__ int                g_list[MAX_B];
__device__ int                g_nrej;

// ---------- Kernel A: token-parallel gather + per-request scan --------------
__global__ void __launch_bounds__(512)
scan_compact(const float* __restrict__ draft_probs,
             const float* __restrict__ target_probs,
             const float* __restrict__ uniform_probs,
             const int*   __restrict__ draft_token_ids,
             const int*   __restrict__ cu,
             const int*   __restrict__ bonus,
             float*       __restrict__ out,
             int B, int NT, int V, int L)
{
    __shared__ int   sid[MAX_NT];
    __shared__ float stp[MAX_NT];
    __shared__ float sdp[MAX_NT];
    __shared__ float su [MAX_NT];
    __shared__ int   scu[MAX_B];
    __shared__ int   wcnt[16];

    const int tid = threadIdx.x;

    for (int r = tid; r < B; r += 512) scu[r] = __ldg(&cu[r]);
    for (int t = tid; t < NT; t += 512) sid[t] = __ldg(&draft_token_ids[t]);
    __syncthreads();

    for (int t = tid; t < NT; t += 512) {
        const int idv = sid[t];
        stp[t] = __ldg(&target_probs[(size_t)t * V + idv]);
        sdp[t] = __ldg(&draft_probs [(size_t)t * V + idv]);
        su [t] = __ldg(&uniform_probs[t]);
    }
    __syncthreads();

    const int r      = tid;
    const bool activ = (r < B);
    int start = 0, end = 0;
    if (activ) { start = (r == 0) ? 0 : scu[r - 1]; end = scu[r]; }
    const int nd  = end - start;
    const int lim = (nd < L) ? nd : L;

    float pi = 1.0f, U = 1.0f;
    int last = -1;
    for (int j = 0; j < lim; j++) {
        const int t = start + j;
        const float dpj = sdp[t];
        const float ratio = (dpj > 0.0f) ? (stp[t] / dpj) : 1.0f;
        pi = fminf(pi * ratio, 1.0f);
        U *= su[t];
        if ((dpj > 0.0f) && (pi >= U)) last = j;
    }

    const int rejected  = (activ && nd > 0 && last != nd - 1) ? 1 : 0;
    const int write_col = rejected ? (last + 1) : nd;

    if (activ) {
        float* orow = out + (size_t)r * (L + 1);
        for (int j = 0; j <= L; j++) {
            float v = -1.0f;
            if (j < L && j <= last) v = (float)sid[start + j];
            orow[j] = v;
        }
        if (!rejected) orow[write_col] = (float)__ldg(&bonus[r]);
    }

    int rec = start + last + 1;
    rec = (rec < 0) ? 0 : rec;
    rec = (rec > NT - 1) ? (NT - 1) : rec;

    const int warp = tid >> 5, lane = tid & 31;
    const unsigned ball = __ballot_sync(0xffffffffu, rejected);
    const int rank = __popc(ball & ((1u << lane) - 1));
    if (lane == 0) wcnt[warp] = __popc(ball);
    __syncthreads();
    int base = 0, total = 0;
    #pragma unroll
    for (int w = 0; w < 16; w++) {
        if (w < warp) base += wcnt[w];
        total += wcnt[w];
    }
    if (rejected)
        g_list[base + rank] = r | (write_col << 8) | (rec << 12);
    if (tid == 0) g_nrej = total;
}

// ---- shared epilogue: block reduce + packed-key atomic combine -------------
__device__ __forceinline__ void combine_and_write(
    float best, int bidx, int r, int pos, int nact,
    float* __restrict__ out, int L)
{
    const int tid = threadIdx.x;
    #pragma unroll
    for (int off = 16; off > 0; off >>= 1) {
        const float ov = __shfl_down_sync(0xffffffffu, best, off);
        const int   oi = __shfl_down_sync(0xffffffffu, bidx, off);
        if (ov > best || (ov == best && oi < bidx)) { best = ov; bidx = oi; }
    }
    __shared__ float wv[TPB / 32];
    __shared__ int   wi[TPB / 32];
    const int warp = tid >> 5, lane = tid & 31;
    if (lane == 0) { wv[warp] = best; wi[warp] = bidx; }
    __syncthreads();

    if (tid == 0) {
        #pragma unroll
        for (int w = 1; w < TPB / 32; w++) {
            if (wv[w] > best || (wv[w] == best && wi[w] < bidx)) {
                best = wv[w]; bidx = wi[w];
            }
        }
        const unsigned long long key =
            ((unsigned long long)__float_as_uint(best) << 32) |
            (unsigned long long)(~(unsigned)bidx);
        atomicMax(&g_key[r], key);
        __threadfence();
        const int old = atomicAdd(&g_cnt[r], 1);
        if (old == nact - 1) {
            const unsigned long long k = atomicMax(&g_key[r], 0ULL);
            const int idx = (int)(~(unsigned)(k & 0xffffffffULL));
            out[(size_t)r * (L + 1) + pos] = (float)idx;
            g_key[r] = 0ULL;
            g_cnt[r] = 0;
        }
    }
}

// ---------- Kernel B (specialized): KF unmasked front-issued loads ----------
template<int KF>
__global__ void __launch_bounds__(TPB)
argmax_spec(const float* __restrict__ target_probs,
            float* __restrict__ out, int V, int L)
{
    const int row = blockIdx.x / SSPLIT;
    if (row >= g_nrej) return;
    const int s   = blockIdx.x % SSPLIT;
    const int tid = threadIdx.x;

    const int e   = g_list[row];
    const int r   = e & 0xff;
    const int pos = (e >> 8) & 0xf;
    const int rec = e >> 12;

    const float4* row4 = reinterpret_cast<const float4*>(
        target_probs + (size_t)rec * V);
    const int n4beg = s * (KF * TPB);          // chunk = KF*TPB float4, exact

    float m[KF];
    const float4* p = row4 + n4beg + tid;
    // KF front-issued unmasked loads; each v dies into its max4 immediately
    #pragma unroll
    for (int k = 0; k < KF; k++) {
        const float4 v = __ldg(p + k * TPB);
        m[k] = fmaxf(fmaxf(v.x, v.y), fmaxf(v.z, v.w));
    }

    float M = m[0];
    #pragma unroll
    for (int k = 1; k < KF; k++) M = fmaxf(M, m[k]);

    // smallest k with m[k]==M (global index grows with k)
    int kwin = KF - 1;
    #pragma unroll
    for (int k = KF - 2; k >= 0; k--) if (m[k] == M) kwin = k;
    const int bb4 = n4beg + tid + kwin * TPB;

    // decode winning lane (L1-hit reload), first occurrence within float4
    const float4 v = __ldg(&row4[bb4]);
    const int bidx = (bb4 << 2) + ((v.x == M) ? 0 : (v.y == M) ? 1
                                 : (v.z == M) ? 2 : 3);

    combine_and_write(M, bidx, r, pos, SSPLIT, out, L);
}

// ---------- Kernel B (generic fallback): proven batch-8 masked body ---------
__global__ void __launch_bounds__(TPB)
argmax_generic(const float* __restrict__ target_probs,
               float* __restrict__ out, int V, int L)
{
    const int row = blockIdx.x / GSPLIT;
    if (row >= g_nrej) return;
    const int s   = blockIdx.x % GSPLIT;
    const int tid = threadIdx.x;

    const int e   = g_list[row];
    const int r   = e & 0xff;
    const int pos = (e >> 8) & 0xf;
    const int rec = e >> 12;

    const int chunk = (((V + GSPLIT - 1) / GSPLIT) + 3) & ~3;
    const int nact  = (V + chunk - 1) / chunk;
    if (s >= nact) return;
    const int beg = s * chunk;
    const int fin = min(V, beg + chunk);

    const float*  rowp = target_probs + (size_t)rec * V;
    const float4* row4 = reinterpret_cast<const float4*>(rowp);
    const int n4beg = beg >> 2;
    const int n4end = fin >> 2;

    float  best  = -1.0f;
    int    bbase = -1;
    float4 bv    = make_float4(0.f, 0.f, 0.f, 0.f);

    for (int i0 = n4beg + tid; i0 < n4end; i0 += BATCH * TPB) {
        float4 vv[BATCH];
        #pragma unroll
        for (int k = 0; k < BATCH; k++) {
            const int ik = i0 + k * TPB;
            const int safe = (ik < n4end) ? ik : i0;
            vv[k] = __ldg(&row4[safe]);
        }
        #pragma unroll
        for (int k = 0; k < BATCH; k++) {
            const int ik = i0 + k * TPB;
            const float m = fmaxf(fmaxf(vv[k].x, vv[k].y),
                                  fmaxf(vv[k].z, vv[k].w));
            if ((ik < n4end) && (m > best)) {
                best = m; bbase = ik << 2; bv = vv[k];
            }
        }
    }

    int bidx = 0x7fffffff;
    if (bbase >= 0) {
        bidx = bbase + ((bv.x == best) ? 0 : (bv.y == best) ? 1
                      : (bv.z == best) ? 2 : 3);
    }
    {
        const int t0 = n4end << 2;
        if (tid < fin - t0) {
            const float vv2 = __ldg(&rowp[t0 + tid]);
            const int   ii  = t0 + tid;
            if (vv2 > best || (vv2 == best && ii < bidx)) { best = vv2; bidx = ii; }
        }
    }

    combine_and_write(best, bidx, r, pos, nact, out, L);
}

extern "C" void kernel_launch(void* const* d_in, const int* in_sizes, int n_in,
                              void* d_out, int out_size) {
    const float* draft_probs     = (const float*)d_in[0];
    const float* target_probs    = (const float*)d_in[1];
    const float* uniform_probs   = (const float*)d_in[2];
    const int*   draft_token_ids = (const int*)  d_in[3];
    const int*   cu              = (const int*)  d_in[4];
    const int*   bonus           = (const int*)  d_in[5];
    float*       out             = (float*)d_out;

    const int NT = in_sizes[3];
    const int B  = in_sizes[4];
    const int V  = in_sizes[0] / NT;
    const int L  = out_size / B - 1;

    scan_compact<<<1, 512>>>(draft_probs, target_probs, uniform_probs,
                             draft_token_ids, cu, bonus, out, B, NT, V, L);

    if (V == SSPLIT * TPB * 4 * 5) {           // V == 128000: exact KF=5 path
        argmax_spec<5><<<B * SSPLIT, TPB>>>(target_probs, out, V, L);
    } else {
        argmax_generic<<<B * GSPLIT, TPB>>>(target_probs, out, V, L);
    }
}